// round 5
// baseline (speedup 1.0000x reference)
#include <cuda_runtime.h>

#define N197   197
#define NN     38809        // 197*197
#define NBATCH 32
#define NLAY   2            // processed layers: 4 and 11
#define KDISC  9702         // int(197*197*0.25)
#define PADR   256
#define PADC   208
#define NTF    1024

__device__ float g_norm[NLAY * NBATCH * PADR * PADC];  // normalized, zero-padded

// ---------------------------------------------------------------------------
// block-wide "pick the bucket containing rank" over nb counters
// s_out: [0]=chosen bucket, [1]=rank within bucket, [2]=count below
// ---------------------------------------------------------------------------
template<int PER>
__device__ __forceinline__ void block_pick(const unsigned* cnts, int nb, int rank,
                                           unsigned* wtot, int* s_out) {
    const int t = threadIdx.x, lane = t & 31, wid = t >> 5;
    const int base = t * PER;
    unsigned h[PER];
    unsigned sum = 0;
    if (base < nb) {
#pragma unroll
        for (int j = 0; j < PER; j++) { h[j] = cnts[base + j]; sum += h[j]; }
    }
    unsigned x = sum;
#pragma unroll
    for (int o = 1; o < 32; o <<= 1) {
        unsigned y = __shfl_up_sync(0xffffffffu, x, o);
        if (lane >= o) x += y;
    }
    if (lane == 31) wtot[wid] = x;
    __syncthreads();
    if (wid == 0) {
        unsigned y = wtot[lane];
#pragma unroll
        for (int o = 1; o < 32; o <<= 1) {
            unsigned z = __shfl_up_sync(0xffffffffu, y, o);
            if (lane >= o) y += z;
        }
        wtot[lane] = y;
    }
    __syncthreads();
    unsigned excl = x - sum + (wid ? wtot[wid - 1] : 0u);
    if (base < nb && (unsigned)rank >= excl && (unsigned)rank < excl + sum) {
        unsigned c = excl; int ch = base;
#pragma unroll
        for (int j = 0; j < PER; j++) {
            if (c + h[j] > (unsigned)rank) { ch = base + j; break; }
            c += h[j];
        }
        s_out[0] = ch; s_out[1] = rank - (int)c; s_out[2] = (int)c;
    }
    __syncthreads();
}

// ---------------------------------------------------------------------------
// 1) mega-fused: DRAM->mean->smem (+hist0 under DRAM shadow) -> pick ->
//    hist1 -> pick -> [rare round-2/tie pass] -> discard+rowsum -> norm write
// ---------------------------------------------------------------------------
__global__ void __launch_bounds__(NTF) fused_kernel(const float* __restrict__ in) {
    extern __shared__ float sm[];          // NN floats
    __shared__ unsigned hist[4096];
    __shared__ unsigned wtot[32];
    __shared__ int s_pick[3];
    __shared__ float rowden[N197];

    const int lb = blockIdx.x;             // 0..63 = li*32 + b
    const int t = threadIdx.x, lane = t & 31, wid = t >> 5;
    const int li = lb >> 5, b = lb & 31;
    const int layer = li ? 11 : 4;
    const float* __restrict__ base = in + ((long)(layer * NBATCH + b) * 12) * NN;

    for (int i = t; i < 4096; i += NTF) hist[i] = 0u;
    __syncthreads();

    // ---- head mean straight from HBM into smem + round-0 hist (top 12 bits) ----
    const int ITER = (NN + NTF - 1) / NTF; // 38
    for (int k = 0; k < ITER; k++) {
        int p = k * NTF + t;
        bool valid = p < NN;
        float s = 0.f;
        if (valid) {
#pragma unroll
            for (int h = 0; h < 12; h++) s += __ldg(&base[(long)h * NN + p]);
            s *= (1.0f / 12.0f);
            sm[p] = s;
        }
        unsigned key = __float_as_uint(s) >> 20;
        unsigned m = __ballot_sync(0xffffffffu, valid);
        if (valid) {
            unsigned grp = __match_any_sync(m, key);
            if (lane == (int)__ffs(grp) - 1) atomicAdd(&hist[key], __popc(grp));
        }
    }
    __syncthreads();

    // ---- round 0 pick ----
    block_pick<4>(hist, 4096, KDISC - 1, wtot, s_pick);
    const int B1 = s_pick[0];
    int rank = s_pick[1];

    for (int i = t; i < 4096; i += NTF) hist[i] = 0u;
    __syncthreads();

    // ---- round 1 hist: bits 19..8 of keys in bucket B1 (sparse -> plain atomics) ----
    for (int k = 0; k < ITER; k++) {
        int i = k * NTF + t;
        if (i < NN) {
            unsigned key = __float_as_uint(sm[i]);
            if ((int)(key >> 20) == B1) atomicAdd(&hist[(key >> 8) & 0xFFFu], 1u);
        }
    }
    __syncthreads();

    block_pick<4>(hist, 4096, rank, wtot, s_pick);
    const int B2 = s_pick[0];
    rank = s_pick[1];
    const unsigned K24 = ((unsigned)B1 << 12) | (unsigned)B2;
    const unsigned ties2 = hist[B2];

    int mode;           // 0: zero key24<=K24 | 1: zero key<=T | 2: zero key<T (ties pre-zeroed)
    unsigned T = 0;
    if (ties2 == 1u) {
        mode = 0;       // unique kth element at 24-bit granularity
    } else {
        // ---- round 2: low 8 bits among key24==K24 ----
        for (int i = t; i < 256; i += NTF) hist[i] = 0u;
        __syncthreads();
        for (int k = 0; k < ITER; k++) {
            int i = k * NTF + t;
            if (i < NN) {
                unsigned key = __float_as_uint(sm[i]);
                if ((key >> 8) == K24) atomicAdd(&hist[key & 0xFFu], 1u);
            }
        }
        __syncthreads();
        block_pick<1>(hist, 256, rank, wtot, s_pick);
        const int B3 = s_pick[0];
        const int rank3 = s_pick[1];
        T = (K24 << 8) | (unsigned)B3;
        const unsigned ties3 = hist[B3];
        const int need = rank3 + 1;            // #(==T) among the k smallest
        if ((unsigned)need == ties3) {
            mode = 1;
        } else {
            mode = 2;
            // index-ordered tie zeroing: contiguous segments + block scan
            const int SEG = (NN + NTF - 1) / NTF;
            int start = t * SEG, end = min(start + SEG, NN);
            int cnt = 0;
            for (int i = start; i < end; i++)
                if (__float_as_uint(sm[i]) == T) cnt++;
            int x = cnt;
#pragma unroll
            for (int o = 1; o < 32; o <<= 1) {
                int y = __shfl_up_sync(0xffffffffu, x, o);
                if (lane >= o) x += y;
            }
            if (lane == 31) wtot[wid] = (unsigned)x;
            __syncthreads();
            if (wid == 0) {
                unsigned y = wtot[lane];
#pragma unroll
                for (int o = 1; o < 32; o <<= 1) {
                    unsigned z = __shfl_up_sync(0xffffffffu, y, o);
                    if (lane >= o) y += z;
                }
                wtot[lane] = y;
            }
            __syncthreads();
            int pre = x - cnt + (wid ? (int)wtot[wid - 1] : 0);
            for (int i = start; i < end; i++) {
                if (__float_as_uint(sm[i]) == T) {
                    if (pre < need && i != 0) sm[i] = 0.f;
                    pre++;
                }
            }
            __syncthreads();
        }
    }

    // ---- discard + row sums in one pass (warp per row) ----
    for (int r = wid; r < N197; r += 32) {
        float s = 0.f;
        const int rowbase = r * N197;
        for (int c = lane; c < N197; c += 32) {
            int i = rowbase + c;
            float v = sm[i];
            unsigned key = __float_as_uint(v);
            bool z = (mode == 0) ? ((key >> 8) <= K24)
                   : (mode == 1) ? (key <= T)
                                 : (key < T);
            if (z && i != 0) { sm[i] = 0.f; v = 0.f; }
            s += v;
        }
#pragma unroll
        for (int o = 16; o; o >>= 1) s += __shfl_xor_sync(0xffffffffu, s, o);
        if (lane == 0) rowden[r] = s + 1.0f;    // the *0.5 cancels: (x+d)/(sum+1)
    }
    __syncthreads();

    // ---- normalized float4 write into zero-padded 256x208 buffer ----
    float4* o4 = (float4*)(g_norm + (long)lb * (PADR * PADC));
    const int NV = PADR * PADC / 4;            // 13312
    const int C4 = PADC / 4;                   // 52
    for (int i = t; i < NV; i += NTF) {
        int r = i / C4;
        int c = (i - r * C4) * 4;
        float4 val = make_float4(0.f, 0.f, 0.f, 0.f);
        if (r < N197) {
            float inv = 1.0f / rowden[r];
            float* e = &val.x;
#pragma unroll
            for (int j = 0; j < 4; j++) {
                int cc = c + j;
                if (cc < N197) e[j] = (sm[r * N197 + cc] + (r == cc ? 1.f : 0.f)) * inv;
            }
        }
        o4[i] = val;
    }
}

// ---------------------------------------------------------------------------
// 2) out[b] = A11[b] @ A4[b] with packed f32x2 FMA (FFMA2) + 8x8 microtile
// ---------------------------------------------------------------------------
#define BM 64
#define BN 64
#define BK 16

#define PACKF2(d, lo, hi) \
    asm("mov.b64 %0, {%1, %2};" : "=l"(d) : "r"(__float_as_uint(lo)), "r"(__float_as_uint(hi)))
#define FMAF2(d, a, bb) \
    asm("fma.rn.f32x2 %0, %1, %2, %0;" : "+l"(d) : "l"(a), "l"(bb))

__global__ void __launch_bounds__(64) gemm_kernel(float* __restrict__ C) {
    const int b = blockIdx.z;
    const float* __restrict__ A  = g_norm + (long)(NBATCH + b) * (PADR * PADC); // layer 11
    const float* __restrict__ Bm = g_norm + (long)b * (PADR * PADC);            // layer 4
    C += (long)b * NN;

    __shared__ float As[BK][BM];       // transposed: As[k][m]
    __shared__ float Bs[BK][BN];

    const int t  = threadIdx.x;        // 0..63
    const int tx = t & 7;              // n-group (8 cols)
    const int ty = t >> 3;             // m-group (8 rows)
    const int row0 = blockIdx.y * BM, col0 = blockIdx.x * BN;

    unsigned long long acc[4][8];      // [m-pair][n]
#pragma unroll
    for (int mp = 0; mp < 4; mp++)
#pragma unroll
        for (int n = 0; n < 8; n++) acc[mp][n] = 0ull;

    for (int k0 = 0; k0 < PADC; k0 += BK) {
#pragma unroll
        for (int c4 = 0; c4 < 4; c4++) {          // As: row t, 16 k values
            float4 a = *(const float4*)&A[(row0 + t) * PADC + k0 + c4 * 4];
            As[c4 * 4 + 0][t] = a.x;
            As[c4 * 4 + 1][t] = a.y;
            As[c4 * 4 + 2][t] = a.z;
            As[c4 * 4 + 3][t] = a.w;
        }
#pragma unroll
        for (int l = 0; l < 4; l++) {             // Bs: 256 float4 / 64 threads
            int idx = t + l * 64;
            int kr = idx >> 4, cq = idx & 15;
            *(float4*)&Bs[kr][cq * 4] =
                *(const float4*)&Bm[(k0 + kr) * PADC + col0 + cq * 4];
        }
        __syncthreads();
#pragma unroll
        for (int kk = 0; kk < BK; kk++) {
            float4 a0 = *(const float4*)&As[kk][ty * 8];
            float4 a1 = *(const float4*)&As[kk][ty * 8 + 4];
            float4 b0 = *(const float4*)&Bs[kk][tx * 8];
            float4 b1 = *(const float4*)&Bs[kk][tx * 8 + 4];
            unsigned long long ap[4];
            PACKF2(ap[0], a0.x, a0.y);
            PACKF2(ap[1], a0.z, a0.w);
            PACKF2(ap[2], a1.x, a1.y);
            PACKF2(ap[3], a1.z, a1.w);
            float bv[8] = {b0.x, b0.y, b0.z, b0.w, b1.x, b1.y, b1.z, b1.w};
#pragma unroll
            for (int n = 0; n < 8; n++) {
                unsigned long long bs;
                PACKF2(bs, bv[n], bv[n]);
#pragma unroll
                for (int mp = 0; mp < 4; mp++) FMAF2(acc[mp][n], ap[mp], bs);
            }
        }
        __syncthreads();
    }

#pragma unroll
    for (int mp = 0; mp < 4; mp++) {
#pragma unroll
        for (int n = 0; n < 8; n++) {
            unsigned ulo, uhi;
            asm("mov.b64 {%0, %1}, %2;" : "=r"(ulo), "=r"(uhi) : "l"(acc[mp][n]));
            int gr = row0 + ty * 8 + mp * 2;
            int gc = col0 + tx * 8 + n;
            if (gc < N197) {
                if (gr < N197)     C[gr * N197 + gc]       = __uint_as_float(ulo);
                if (gr + 1 < N197) C[(gr + 1) * N197 + gc] = __uint_as_float(uhi);
            }
        }
    }
}

// ---------------------------------------------------------------------------
extern "C" void kernel_launch(void* const* d_in, const int* in_sizes, int n_in,
                              void* d_out, int out_size) {
    const float* attn = (const float*)d_in[0];  // (12,32,12,197,197) fp32
    float* out = (float*)d_out;                 // (32,197,197) fp32
    (void)in_sizes; (void)n_in; (void)out_size;

    cudaFuncSetAttribute(fused_kernel, cudaFuncAttributeMaxDynamicSharedMemorySize,
                         NN * (int)sizeof(float));

    fused_kernel<<<NLAY * NBATCH, NTF, NN * sizeof(float)>>>(attn);
    dim3 gg((N197 + BN - 1) / BN, (N197 + BM - 1) / BM, NBATCH);
    gemm_kernel<<<gg, 64>>>(out);
}

// round 6
// speedup vs baseline: 1.1565x; 1.1565x over previous
#include <cuda_runtime.h>

#define N197   197
#define NN     38809        // 197*197
#define NNP    38812        // padded stride (float4-aligned)
#define NBATCH 32
#define NLAY   2            // processed layers: 4 and 11
#define KDISC  9702         // int(197*197*0.25)
#define PADR   256
#define PADC   208
#define NTF    1024

__device__ float    g_attn[NLAY * NBATCH * NNP];
__device__ float    g_norm[NLAY * NBATCH * PADR * PADC];
__device__ unsigned g_hist[NLAY * NBATCH * 4096];

// ---------------------------------------------------------------------------
// 0) zero the global round-0 histograms
// ---------------------------------------------------------------------------
__global__ void zero_hist() {
    for (int i = threadIdx.x; i < 4096; i += blockDim.x)
        g_hist[blockIdx.x * 4096 + i] = 0u;
}

// ---------------------------------------------------------------------------
// 1) mean over heads + round-0 histogram (top 12 float bits) under DRAM shadow
// ---------------------------------------------------------------------------
__global__ void __launch_bounds__(256) mean_kernel(const float* __restrict__ in) {
    __shared__ unsigned hist[4096];
    for (int i = threadIdx.x; i < 4096; i += 256) hist[i] = 0u;
    __syncthreads();

    int lb = blockIdx.y;                 // 0..63 = li*32 + b
    int li = lb >> 5, b = lb & 31;
    int layer = li ? 11 : 4;
    const float* __restrict__ base = in + ((long)(layer * NBATCH + b) * 12) * NN;
    float* dst = g_attn + (long)lb * NNP;
    const int lane   = threadIdx.x & 31;
    const int stride = gridDim.x * 256;
    const int ITER   = (NN + stride - 1) / stride;

    for (int k = 0; k < ITER; k++) {
        int p = k * stride + blockIdx.x * 256 + threadIdx.x;
        bool valid = p < NN;
        float s = 0.f;
        if (valid) {
#pragma unroll
            for (int h = 0; h < 12; h++) s += __ldg(&base[(long)h * NN + p]);
            s *= (1.0f / 12.0f);
            dst[p] = s;
        }
        unsigned key = __float_as_uint(s) >> 20;
        unsigned m = __ballot_sync(0xffffffffu, valid);
        if (valid) {
            unsigned grp = __match_any_sync(m, key);
            if (lane == (int)__ffs(grp) - 1) atomicAdd(&hist[key], __popc(grp));
        }
    }
    __syncthreads();
    for (int i = threadIdx.x; i < 4096; i += 256) {
        unsigned c = hist[i];
        if (c) atomicAdd(&g_hist[lb * 4096 + i], c);
    }
}

// ---------------------------------------------------------------------------
// block-wide "pick the bucket containing rank"
// s_out: [0]=chosen bucket, [1]=rank within bucket, [2]=count below
// ---------------------------------------------------------------------------
template<int PER>
__device__ __forceinline__ void block_pick(const unsigned* cnts, int nb, int rank,
                                           unsigned* wtot, int* s_out) {
    const int t = threadIdx.x, lane = t & 31, wid = t >> 5;
    const int base = t * PER;
    unsigned h[PER];
    unsigned sum = 0;
    if (base < nb) {
#pragma unroll
        for (int j = 0; j < PER; j++) { h[j] = cnts[base + j]; sum += h[j]; }
    }
    unsigned x = sum;
#pragma unroll
    for (int o = 1; o < 32; o <<= 1) {
        unsigned y = __shfl_up_sync(0xffffffffu, x, o);
        if (lane >= o) x += y;
    }
    if (lane == 31) wtot[wid] = x;
    __syncthreads();
    if (wid == 0) {
        unsigned y = wtot[lane];
#pragma unroll
        for (int o = 1; o < 32; o <<= 1) {
            unsigned z = __shfl_up_sync(0xffffffffu, y, o);
            if (lane >= o) y += z;
        }
        wtot[lane] = y;
    }
    __syncthreads();
    unsigned excl = x - sum + (wid ? wtot[wid - 1] : 0u);
    if (base < nb && (unsigned)rank >= excl && (unsigned)rank < excl + sum) {
        unsigned c = excl; int ch = base;
#pragma unroll
        for (int j = 0; j < PER; j++) {
            if (c + h[j] > (unsigned)rank) { ch = base + j; break; }
            c += h[j];
        }
        s_out[0] = ch; s_out[1] = rank - (int)c; s_out[2] = (int)c;
    }
    __syncthreads();
}

// ---------------------------------------------------------------------------
// 2) fused: pick0 -> load(L2)+hist1 -> pick1 -> [rare round-2/ties]
//    -> discard+rowsum -> normalized padded write
// ---------------------------------------------------------------------------
__global__ void __launch_bounds__(NTF) fused_kernel() {
    extern __shared__ float sm[];          // NN floats
    __shared__ unsigned hist[4096];
    __shared__ unsigned wtot[32];
    __shared__ int s_pick[3];
    __shared__ float rowden[N197];

    const int lb = blockIdx.x;
    const int t = threadIdx.x, lane = t & 31, wid = t >> 5;

    // ---- round 0 pick from global histogram ----
    block_pick<4>(&g_hist[lb * 4096], 4096, KDISC - 1, wtot, s_pick);
    const int B1 = s_pick[0];
    int rank = s_pick[1];

    for (int i = t; i < 4096; i += NTF) hist[i] = 0u;
    __syncthreads();

    // ---- load matrix to smem + round-1 hist (plain atomics; ~6% hit rate) ----
    const float* src = g_attn + (long)lb * NNP;
    const float4* s4 = (const float4*)src;
    float4* d4 = (float4*)sm;
    const int N4 = NN / 4;                 // 9702
    const int IT4 = (N4 + NTF - 1) / NTF;  // 10
    for (int k = 0; k < IT4; k++) {
        int i = k * NTF + t;
        if (i < N4) {
            float4 a = s4[i];
            d4[i] = a;
            const float vv[4] = {a.x, a.y, a.z, a.w};
#pragma unroll
            for (int j = 0; j < 4; j++) {
                unsigned key = __float_as_uint(vv[j]);
                if ((int)(key >> 20) == B1) atomicAdd(&hist[(key >> 8) & 0xFFFu], 1u);
            }
        }
    }
    if (t == 0) {                          // tail element 38808
        float v = src[NN - 1]; sm[NN - 1] = v;
        unsigned key = __float_as_uint(v);
        if ((int)(key >> 20) == B1) atomicAdd(&hist[(key >> 8) & 0xFFFu], 1u);
    }
    __syncthreads();

    block_pick<4>(hist, 4096, rank, wtot, s_pick);
    const int B2 = s_pick[0];
    rank = s_pick[1];
    const unsigned K24 = ((unsigned)B1 << 12) | (unsigned)B2;
    const unsigned ties2 = hist[B2];

    int mode;           // 0: zero key24<=K24 | 1: zero key<=T | 2: zero key<T (ties pre-zeroed)
    unsigned T = 0;
    if (ties2 == 1u) {
        mode = 0;       // unique kth element at 24-bit granularity
    } else {
        // ---- round 2: low 8 bits among key24==K24 ----
        for (int i = t; i < 256; i += NTF) hist[i] = 0u;
        __syncthreads();
        const int IT = (NN + NTF - 1) / NTF;   // 38
        for (int k = 0; k < IT; k++) {
            int i = k * NTF + t;
            if (i < NN) {
                unsigned key = __float_as_uint(sm[i]);
                if ((key >> 8) == K24) atomicAdd(&hist[key & 0xFFu], 1u);
            }
        }
        __syncthreads();
        block_pick<1>(hist, 256, rank, wtot, s_pick);
        const int B3 = s_pick[0];
        const int rank3 = s_pick[1];
        T = (K24 << 8) | (unsigned)B3;
        const unsigned ties3 = hist[B3];
        const int need = rank3 + 1;            // #(==T) among the k smallest
        if ((unsigned)need == ties3) {
            mode = 1;
        } else {
            mode = 2;
            const int SEG = (NN + NTF - 1) / NTF;
            int start = t * SEG, end = min(start + SEG, NN);
            int cnt = 0;
            for (int i = start; i < end; i++)
                if (__float_as_uint(sm[i]) == T) cnt++;
            int x = cnt;
#pragma unroll
            for (int o = 1; o < 32; o <<= 1) {
                int y = __shfl_up_sync(0xffffffffu, x, o);
                if (lane >= o) x += y;
            }
            if (lane == 31) wtot[wid] = (unsigned)x;
            __syncthreads();
            if (wid == 0) {
                unsigned y = wtot[lane];
#pragma unroll
                for (int o = 1; o < 32; o <<= 1) {
                    unsigned z = __shfl_up_sync(0xffffffffu, y, o);
                    if (lane >= o) y += z;
                }
                wtot[lane] = y;
            }
            __syncthreads();
            int pre = x - cnt + (wid ? (int)wtot[wid - 1] : 0);
            for (int i = start; i < end; i++) {
                if (__float_as_uint(sm[i]) == T) {
                    if (pre < need && i != 0) sm[i] = 0.f;
                    pre++;
                }
            }
            __syncthreads();
        }
    }

    // ---- discard + row sums in one pass (warp per row) ----
    for (int r = wid; r < N197; r += 32) {
        float s = 0.f;
        const int rowbase = r * N197;
        for (int c = lane; c < N197; c += 32) {
            int i = rowbase + c;
            float v = sm[i];
            unsigned key = __float_as_uint(v);
            bool z = (mode == 0) ? ((key >> 8) <= K24)
                   : (mode == 1) ? (key <= T)
                                 : (key < T);
            if (z && i != 0) { sm[i] = 0.f; v = 0.f; }
            s += v;
        }
#pragma unroll
        for (int o = 16; o; o >>= 1) s += __shfl_xor_sync(0xffffffffu, s, o);
        if (lane == 0) rowden[r] = s + 1.0f;    // the *0.5 cancels: (x+d)/(sum+1)
    }
    __syncthreads();

    // ---- normalized float4 write into zero-padded 256x208 buffer ----
    float4* o4 = (float4*)(g_norm + (long)lb * (PADR * PADC));
    const int NV = PADR * PADC / 4;            // 13312
    const int C4 = PADC / 4;                   // 52
    for (int i = t; i < NV; i += NTF) {
        int r = i / C4;
        int c = (i - r * C4) * 4;
        float4 val = make_float4(0.f, 0.f, 0.f, 0.f);
        if (r < N197) {
            float inv = 1.0f / rowden[r];
            float* e = &val.x;
#pragma unroll
            for (int j = 0; j < 4; j++) {
                int cc = c + j;
                if (cc < N197) e[j] = (sm[r * N197 + cc] + (r == cc ? 1.f : 0.f)) * inv;
            }
        }
        o4[i] = val;
    }
}

// ---------------------------------------------------------------------------
// 3) out[b] = A11[b] @ A4[b]: 128x64 tile, 256 threads, 8x4 microtile, f32x2
// ---------------------------------------------------------------------------
#define BM 128
#define BN 64
#define BK 16

#define PACKF2(d, lo, hi) \
    asm("mov.b64 %0, {%1, %2};" : "=l"(d) : "r"(__float_as_uint(lo)), "r"(__float_as_uint(hi)))
#define FMAF2(d, a, bb) \
    asm("fma.rn.f32x2 %0, %1, %2, %0;" : "+l"(d) : "l"(a), "l"(bb))

__global__ void __launch_bounds__(256) gemm_kernel(float* __restrict__ C) {
    const int b = blockIdx.z;
    const float* __restrict__ A  = g_norm + (long)(NBATCH + b) * (PADR * PADC); // layer 11
    const float* __restrict__ Bm = g_norm + (long)b * (PADR * PADC);            // layer 4
    C += (long)b * NN;

    __shared__ float As[BK][BM + 4];   // transposed: As[k][m], padded vs bank conflicts
    __shared__ float Bs[BK][BN];

    const int t  = threadIdx.x;        // 0..255
    const int tx = t & 15;             // n-group: 4 cols
    const int ty = t >> 4;             // m-group: 8 rows
    const int row0 = blockIdx.y * BM, col0 = blockIdx.x * BN;

    unsigned long long acc[4][4];      // [m-pair][n]
#pragma unroll
    for (int mp = 0; mp < 4; mp++)
#pragma unroll
        for (int n = 0; n < 4; n++) acc[mp][n] = 0ull;

    for (int k0 = 0; k0 < PADC; k0 += BK) {
#pragma unroll
        for (int l = 0; l < 2; l++) {             // As: 512 float4 / 256 threads
            int idx = t + l * 256;
            int r = idx >> 2, q = idx & 3;        // r: 0..127, q: k-quad
            float4 a = *(const float4*)&A[(row0 + r) * PADC + k0 + q * 4];
            As[q * 4 + 0][r] = a.x;
            As[q * 4 + 1][r] = a.y;
            As[q * 4 + 2][r] = a.z;
            As[q * 4 + 3][r] = a.w;
        }
        {                                         // Bs: 256 float4 / 256 threads
            int kr = t >> 4, cq = t & 15;
            *(float4*)&Bs[kr][cq * 4] =
                *(const float4*)&Bm[(k0 + kr) * PADC + col0 + cq * 4];
        }
        __syncthreads();
#pragma unroll
        for (int kk = 0; kk < BK; kk++) {
            float4 a0 = *(const float4*)&As[kk][ty * 8];
            float4 a1 = *(const float4*)&As[kk][ty * 8 + 4];
            float4 b0 = *(const float4*)&Bs[kk][tx * 4];
            unsigned long long ap[4];
            PACKF2(ap[0], a0.x, a0.y);
            PACKF2(ap[1], a0.z, a0.w);
            PACKF2(ap[2], a1.x, a1.y);
            PACKF2(ap[3], a1.z, a1.w);
            float bv[4] = {b0.x, b0.y, b0.z, b0.w};
#pragma unroll
            for (int n = 0; n < 4; n++) {
                unsigned long long bs;
                PACKF2(bs, bv[n], bv[n]);
#pragma unroll
                for (int mp = 0; mp < 4; mp++) FMAF2(acc[mp][n], ap[mp], bs);
            }
        }
        __syncthreads();
    }

#pragma unroll
    for (int mp = 0; mp < 4; mp++) {
#pragma unroll
        for (int n = 0; n < 4; n++) {
            unsigned ulo, uhi;
            asm("mov.b64 {%0, %1}, %2;" : "=r"(ulo), "=r"(uhi) : "l"(acc[mp][n]));
            int gr = row0 + ty * 8 + mp * 2;
            int gc = col0 + tx * 4 + n;
            if (gc < N197) {
                if (gr < N197)     C[gr * N197 + gc]       = __uint_as_float(ulo);
                if (gr + 1 < N197) C[(gr + 1) * N197 + gc] = __uint_as_float(uhi);
            }
        }
    }
}

// ---------------------------------------------------------------------------
extern "C" void kernel_launch(void* const* d_in, const int* in_sizes, int n_in,
                              void* d_out, int out_size) {
    const float* attn = (const float*)d_in[0];  // (12,32,12,197,197) fp32
    float* out = (float*)d_out;                 // (32,197,197) fp32
    (void)in_sizes; (void)n_in; (void)out_size;

    cudaFuncSetAttribute(fused_kernel, cudaFuncAttributeMaxDynamicSharedMemorySize,
                         NN * (int)sizeof(float));

    zero_hist<<<NLAY * NBATCH, 256>>>();
    dim3 gm(40, NLAY * NBATCH);
    mean_kernel<<<gm, 256>>>(attn);
    fused_kernel<<<NLAY * NBATCH, NTF, NN * sizeof(float)>>>();
    dim3 gg((N197 + BN - 1) / BN, (N197 + BM - 1) / BM, NBATCH);
    gemm_kernel<<<gg, 256>>>(out);
}